// round 9
// baseline (speedup 1.0000x reference)
#include <cuda_runtime.h>
#include <cuda_fp16.h>

#define BB    2
#define CC    64
#define NN    16384
#define KK    16
#define COUT  64
#define RR    128           // rows of combined matrix [W1-W2 ; W2]
#define TNB   128           // GEMM nodes per block

typedef unsigned long long ull;

// ---------------- scratch (device globals; no allocation allowed) ----------
__device__ float  g_mean[BB][CC];
__device__ float  g_cvec[BB][COUT];
__device__ float  g_Mt[CC][RR];                // transposed combined matrix [c][r]
__device__ __half g_Yh[(size_t)BB * NN * RR];  // 8 MB transformed features (fp16)
__device__ int    g_is64;

// ---------------- f32x2 helpers (sm_103a packed fp32 FMA) -------------------
#define FMA_F32X2(d, a, b) \
    asm("fma.rn.f32x2 %0, %1, %2, %0;" : "+l"(d) : "l"(a), "l"(b))

__device__ __forceinline__ ull pack2(float lo, float hi) {
    ull r;
    asm("mov.b64 %0, {%1, %2};" : "=l"(r) : "f"(lo), "f"(hi));
    return r;
}

// ---------------- dtype detection for edge_index ---------------------------
__global__ void detect_kernel(const void* e) {
    const ull* p = (const ull*)e;
    int is64 = 1;
    #pragma unroll
    for (int i = 0; i < 8; i++)
        if (p[i] >= (ull)NN) is64 = 0;
    g_is64 = is64;
}

// ---------------- mean over nodes: g_mean[b][c] -----------------------------
// One block per (b,c) row. 16 LDG.128 fully unrolled, 4 independent
// accumulators -> MLP 16 per thread; shuffle+smem reduce.
__global__ __launch_bounds__(256) void mean_kernel(const float* __restrict__ x) {
    int row = blockIdx.x;                 // b*CC + c
    const float4* xr = (const float4*)(x + (size_t)row * NN);
    int tid = threadIdx.x;

    float4 v[16];
    #pragma unroll
    for (int it = 0; it < 16; it++)
        v[it] = xr[tid + it * 256];

    float s0 = 0.f, s1 = 0.f, s2 = 0.f, s3 = 0.f;
    #pragma unroll
    for (int it = 0; it < 16; it += 4) {
        s0 += v[it    ].x + v[it    ].y + v[it    ].z + v[it    ].w;
        s1 += v[it + 1].x + v[it + 1].y + v[it + 1].z + v[it + 1].w;
        s2 += v[it + 2].x + v[it + 2].y + v[it + 2].z + v[it + 2].w;
        s3 += v[it + 3].x + v[it + 3].y + v[it + 3].z + v[it + 3].w;
    }
    float s = (s0 + s1) + (s2 + s3);

    #pragma unroll
    for (int off = 16; off > 0; off >>= 1)
        s += __shfl_xor_sync(0xFFFFFFFFu, s, off);

    __shared__ float sm[8];
    if ((tid & 31) == 0) sm[tid >> 5] = s;
    __syncthreads();
    if (tid == 0) {
        float t = 0.f;
        #pragma unroll
        for (int w = 0; w < 8; w++) t += sm[w];
        ((float*)g_mean)[row] = t * (1.0f / NN);
    }
}

// ---------------- build Mt and cvec ----------------------------------------
__global__ __launch_bounds__(128) void prep_kernel(const float* __restrict__ W,
                                                   const float* __restrict__ bias) {
    int t = threadIdx.x;  // 0..127
    for (int c = 0; c < CC; c++) {
        float v;
        if (t < 64) v = W[t * 192 + c] - W[t * 192 + 64 + c];   // W1 - W2
        else        v = W[(t - 64) * 192 + 64 + c];             // W2
        g_Mt[c][t] = v;
    }
    int b = t >> 6, o = t & 63;
    float s = bias[o];
    #pragma unroll 8
    for (int c = 0; c < CC; c++)
        s = fmaf(W[o * 192 + 128 + c], g_mean[b][c], s);        // W3 . mean
    g_cvec[b][o] = s;
}

// ---------------- GEMM: Yh[b][n][r] = sum_c Mt[c][r] * x[b][c][n] -----------
// (measured-best config: 23.2us) grid (128, 2), 2 blocks/SM, 64 KB smem.
// Per-thread tile: 8 n (4 f32x2 pairs) x 8 r, m packed in registers.
__global__ __launch_bounds__(256, 2) void gemm_kernel(const float* __restrict__ x) {
    __shared__ __align__(16) float Ms[CC][RR];    // 32 KB
    __shared__ __align__(16) float Xs[CC][TNB];   // 32 KB
    int b   = blockIdx.y;
    int n0  = blockIdx.x * TNB;
    int tid = threadIdx.x;

    for (int i = tid; i < CC * RR / 4; i += 256)
        ((float4*)Ms)[i] = ((const float4*)g_Mt)[i];
    const float* xb = x + (size_t)b * CC * NN;
    for (int i = tid; i < CC * TNB / 4; i += 256) {
        int c = i >> 5, j = i & 31;   // TNB/4 = 32
        ((float4*)&Xs[c][0])[j] = ((const float4*)(xb + (size_t)c * NN + n0))[j];
    }
    __syncthreads();

    int rg = tid & 15;    // r = rg*8 .. +7
    int ng = tid >> 4;    // n = n0 + ng*8 .. +7 (4 node-pairs)
    ull acc[4][8];
    #pragma unroll
    for (int p = 0; p < 4; p++)
        #pragma unroll
        for (int r = 0; r < 8; r++) acc[p][r] = 0ull;

    #pragma unroll 4
    for (int c = 0; c < CC; c++) {
        float4 m0 = *(const float4*)&Ms[c][rg * 8];       // warp-broadcast
        float4 m1 = *(const float4*)&Ms[c][rg * 8 + 4];
        const ull* xr = (const ull*)&Xs[c][ng * 8];
        ull xp[4];
        #pragma unroll
        for (int p = 0; p < 4; p++) xp[p] = xr[p];
        ull mp[8];
        mp[0] = pack2(m0.x, m0.x); mp[1] = pack2(m0.y, m0.y);
        mp[2] = pack2(m0.z, m0.z); mp[3] = pack2(m0.w, m0.w);
        mp[4] = pack2(m1.x, m1.x); mp[5] = pack2(m1.y, m1.y);
        mp[6] = pack2(m1.z, m1.z); mp[7] = pack2(m1.w, m1.w);
        #pragma unroll
        for (int p = 0; p < 4; p++)
            #pragma unroll
            for (int r = 0; r < 8; r++)
                FMA_F32X2(acc[p][r], xp[p], mp[r]);
    }

    __half* Yb = g_Yh + (size_t)b * NN * RR;
    #pragma unroll
    for (int p = 0; p < 4; p++) {
        #pragma unroll
        for (int s = 0; s < 2; s++) {
            int n = n0 + ng * 8 + 2 * p + s;
            float v[8];
            #pragma unroll
            for (int r = 0; r < 8; r++) {
                uint2 u = *(uint2*)&acc[p][r];
                v[r] = __uint_as_float(s == 0 ? u.x : u.y);
            }
            __half2 h0 = __floats2half2_rn(v[0], v[1]);
            __half2 h1 = __floats2half2_rn(v[2], v[3]);
            __half2 h2 = __floats2half2_rn(v[4], v[5]);
            __half2 h3 = __floats2half2_rn(v[6], v[7]);
            uint4 pk;
            pk.x = *(unsigned*)&h0; pk.y = *(unsigned*)&h1;
            pk.z = *(unsigned*)&h2; pk.w = *(unsigned*)&h3;
            *(uint4*)(Yb + (size_t)n * RR + rg * 8) = pk;
        }
    }
}

// ---------------- gather + max-relu epilogue --------------------------------
// Block 256 thr = 8 warps, 64 nodes/block; warp handles 8 nodes as 4 pairs
// (2 nodes interleaved -> 64 outstanding half2 loads per iteration).
__global__ __launch_bounds__(256) void gather_kernel(const void* __restrict__ eidx,
                                                     float* __restrict__ out) {
    int bn   = blockIdx.x;               // 0..511
    int b    = bn >> 8;                  // 256 blocks per batch
    int n0   = (bn & 255) * 64;
    int tid  = threadIdx.x;
    int lane = tid & 31;
    int w    = tid >> 5;

    __shared__ int   s_idx[64][2][KK];   // 8 KB
    __shared__ float s_o[64][65];        // padded, conflict-free

    int is64 = g_is64;
    const long long* e64 = (const long long*)eidx;
    const int*       e32 = (const int*)eidx;
    for (int i = tid; i < 64 * KK; i += 256) {
        int ln = i >> 4, k = i & 15;
        size_t bj = ((size_t)(0 * BB + b) * NN + (n0 + ln)) * KK + k;
        size_t bi = ((size_t)(1 * BB + b) * NN + (n0 + ln)) * KK + k;
        int vi, vj;
        if (is64) { vj = (int)e64[bj]; vi = (int)e64[bi]; }
        else      { vj = e32[bj];      vi = e32[bi]; }
        s_idx[ln][0][k] = vi;            // center   (edge_index[1])
        s_idx[ln][1][k] = vj;            // neighbor (edge_index[0])
    }
    __syncthreads();

    float2 cv = ((const float2*)g_cvec[b])[lane];   // channels 2*lane, 2*lane+1
    const __half* Yb = g_Yh + (size_t)b * NN * RR;

    #pragma unroll
    for (int t = 0; t < 8; t += 2) {
        int lnA = w * 8 + t;
        int lnB = lnA + 1;
        float a0 = 0.f, a1 = 0.f, b0 = 0.f, b1 = 0.f;  // relu floor folded
        #pragma unroll
        for (int k = 0; k < KK; k++) {
            int iA = s_idx[lnA][0][k], jA = s_idx[lnA][1][k];
            int iB = s_idx[lnB][0][k], jB = s_idx[lnB][1][k];
            __half2 hiA = ((const __half2*)(Yb + (size_t)iA * RR))[lane];
            __half2 hjA = ((const __half2*)(Yb + (size_t)jA * RR + 64))[lane];
            __half2 hiB = ((const __half2*)(Yb + (size_t)iB * RR))[lane];
            __half2 hjB = ((const __half2*)(Yb + (size_t)jB * RR + 64))[lane];
            float2 fiA = __half22float2(hiA), fjA = __half22float2(hjA);
            float2 fiB = __half22float2(hiB), fjB = __half22float2(hjB);
            a0 = fmaxf(a0, fiA.x + fjA.x + cv.x);
            a1 = fmaxf(a1, fiA.y + fjA.y + cv.y);
            b0 = fmaxf(b0, fiB.x + fjB.x + cv.x);
            b1 = fmaxf(b1, fiB.y + fjB.y + cv.y);
        }
        s_o[lnA][2 * lane]     = a0;
        s_o[lnA][2 * lane + 1] = a1;
        s_o[lnB][2 * lane]     = b0;
        s_o[lnB][2 * lane + 1] = b1;
    }
    __syncthreads();

    float* ob = out + (size_t)b * COUT * NN;
    for (int i = tid; i < COUT * 64; i += 256) {
        int ch = i >> 6, j = i & 63;
        ob[ch * NN + n0 + j] = s_o[j][ch];
    }
}

// ---------------- launch ----------------------------------------------------
extern "C" void kernel_launch(void* const* d_in, const int* in_sizes, int n_in,
                              void* d_out, int out_size) {
    const float* x    = (const float*)d_in[0];
    const void*  eidx = d_in[1];
    const float* W    = (const float*)d_in[2];
    const float* bias = (const float*)d_in[3];
    float* out = (float*)d_out;

    detect_kernel<<<1, 32>>>(eidx);
    mean_kernel<<<BB * CC, 256>>>(x);
    prep_kernel<<<1, 128>>>(W, bias);
    gemm_kernel<<<dim3(NN / TNB, BB), 256>>>(x);
    gather_kernel<<<BB * NN / 64, 256>>>(eidx, out);
}

// round 12
// speedup vs baseline: 1.5990x; 1.5990x over previous
#include <cuda_runtime.h>
#include <cuda_fp16.h>

#define BB    2
#define CC    64
#define NN    16384
#define KK    16
#define COUT  64
#define RR    128           // rows of combined matrix [W1-W2 ; W2]
#define TNB   128           // GEMM nodes per block

typedef unsigned long long ull;

// ---------------- scratch (device globals; no allocation allowed) ----------
__device__ float  g_mean[BB][CC];
__device__ float  g_cvec[BB][COUT];
__device__ float  g_Mt[CC][RR];                // transposed combined matrix [c][r]
__device__ __half g_Yh[(size_t)BB * NN * RR];  // 8 MB transformed features (fp16)
__device__ int    g_is64;

// ---------------- f32x2 helpers (sm_103a packed fp32 FMA) -------------------
#define FMA_F32X2(d, a, b) \
    asm("fma.rn.f32x2 %0, %1, %2, %0;" : "+l"(d) : "l"(a), "l"(b))

__device__ __forceinline__ ull pack2(float lo, float hi) {
    ull r;
    asm("mov.b64 %0, {%1, %2};" : "=l"(r) : "f"(lo), "f"(hi));
    return r;
}

// ---------------- mean over nodes: g_mean[b][c] -----------------------------
// One block per (b,c) row. 16 LDG.128 batched up front (MLP 16), 4 independent
// accumulators, shuffle+smem reduce.
__global__ __launch_bounds__(256) void mean_kernel(const float* __restrict__ x) {
    int row = blockIdx.x;                 // b*CC + c
    const float4* xr = (const float4*)(x + (size_t)row * NN);
    int tid = threadIdx.x;

    float4 v[16];
    #pragma unroll
    for (int it = 0; it < 16; it++)
        v[it] = xr[tid + it * 256];

    float s0 = 0.f, s1 = 0.f, s2 = 0.f, s3 = 0.f;
    #pragma unroll
    for (int it = 0; it < 16; it += 4) {
        s0 += v[it    ].x + v[it    ].y + v[it    ].z + v[it    ].w;
        s1 += v[it + 1].x + v[it + 1].y + v[it + 1].z + v[it + 1].w;
        s2 += v[it + 2].x + v[it + 2].y + v[it + 2].z + v[it + 2].w;
        s3 += v[it + 3].x + v[it + 3].y + v[it + 3].z + v[it + 3].w;
    }
    float s = (s0 + s1) + (s2 + s3);

    #pragma unroll
    for (int off = 16; off > 0; off >>= 1)
        s += __shfl_xor_sync(0xFFFFFFFFu, s, off);

    __shared__ float sm[8];
    if ((tid & 31) == 0) sm[tid >> 5] = s;
    __syncthreads();
    if (tid == 0) {
        float t = 0.f;
        #pragma unroll
        for (int w = 0; w < 8; w++) t += sm[w];
        ((float*)g_mean)[row] = t * (1.0f / NN);
    }
}

// ---------------- build Mt, cvec, and edge dtype flag -----------------------
__global__ __launch_bounds__(128) void prep_kernel(const float* __restrict__ W,
                                                   const float* __restrict__ bias,
                                                   const void* __restrict__ eidx) {
    int t = threadIdx.x;  // 0..127
    if (t == 0) {
        const ull* p = (const ull*)eidx;
        int is64 = 1;
        #pragma unroll
        for (int i = 0; i < 8; i++)
            if (p[i] >= (ull)NN) is64 = 0;
        g_is64 = is64;
    }
    for (int c = 0; c < CC; c++) {
        float v;
        if (t < 64) v = W[t * 192 + c] - W[t * 192 + 64 + c];   // W1 - W2
        else        v = W[(t - 64) * 192 + 64 + c];             // W2
        g_Mt[c][t] = v;
    }
    int b = t >> 6, o = t & 63;
    float s = bias[o];
    #pragma unroll 8
    for (int c = 0; c < CC; c++)
        s = fmaf(W[o * 192 + 128 + c], g_mean[b][c], s);        // W3 . mean
    g_cvec[b][o] = s;
}

// ---------------- GEMM: Yh[b][n][r] = sum_c Mt[c][r] * x[b][c][n] -----------
// grid (128, 2), 2 blocks/SM, 64 KB smem.
// Per-thread tile: 8 n (4 f32x2 pairs) x 8 r, m packed in registers.
__global__ __launch_bounds__(256, 2) void gemm_kernel(const float* __restrict__ x) {
    __shared__ __align__(16) float Ms[CC][RR];    // 32 KB
    __shared__ __align__(16) float Xs[CC][TNB];   // 32 KB
    int b   = blockIdx.y;
    int n0  = blockIdx.x * TNB;
    int tid = threadIdx.x;

    for (int i = tid; i < CC * RR / 4; i += 256)
        ((float4*)Ms)[i] = ((const float4*)g_Mt)[i];
    const float* xb = x + (size_t)b * CC * NN;
    for (int i = tid; i < CC * TNB / 4; i += 256) {
        int c = i >> 5, j = i & 31;   // TNB/4 = 32
        ((float4*)&Xs[c][0])[j] = ((const float4*)(xb + (size_t)c * NN + n0))[j];
    }
    __syncthreads();

    int rg = tid & 15;    // r = rg*8 .. +7
    int ng = tid >> 4;    // n = n0 + ng*8 .. +7 (4 node-pairs)
    ull acc[4][8];
    #pragma unroll
    for (int p = 0; p < 4; p++)
        #pragma unroll
        for (int r = 0; r < 8; r++) acc[p][r] = 0ull;

    #pragma unroll 4
    for (int c = 0; c < CC; c++) {
        float4 m0 = *(const float4*)&Ms[c][rg * 8];       // warp-broadcast
        float4 m1 = *(const float4*)&Ms[c][rg * 8 + 4];
        const ull* xr = (const ull*)&Xs[c][ng * 8];
        ull xp[4];
        #pragma unroll
        for (int p = 0; p < 4; p++) xp[p] = xr[p];
        ull mp[8];
        mp[0] = pack2(m0.x, m0.x); mp[1] = pack2(m0.y, m0.y);
        mp[2] = pack2(m0.z, m0.z); mp[3] = pack2(m0.w, m0.w);
        mp[4] = pack2(m1.x, m1.x); mp[5] = pack2(m1.y, m1.y);
        mp[6] = pack2(m1.z, m1.z); mp[7] = pack2(m1.w, m1.w);
        #pragma unroll
        for (int p = 0; p < 4; p++)
            #pragma unroll
            for (int r = 0; r < 8; r++)
                FMA_F32X2(acc[p][r], xp[p], mp[r]);
    }

    __half* Yb = g_Yh + (size_t)b * NN * RR;
    #pragma unroll
    for (int p = 0; p < 4; p++) {
        #pragma unroll
        for (int s = 0; s < 2; s++) {
            int n = n0 + ng * 8 + 2 * p + s;
            float v[8];
            #pragma unroll
            for (int r = 0; r < 8; r++) {
                uint2 u = *(uint2*)&acc[p][r];
                v[r] = __uint_as_float(s == 0 ? u.x : u.y);
            }
            __half2 h0 = __floats2half2_rn(v[0], v[1]);
            __half2 h1 = __floats2half2_rn(v[2], v[3]);
            __half2 h2 = __floats2half2_rn(v[4], v[5]);
            __half2 h3 = __floats2half2_rn(v[6], v[7]);
            uint4 pk;
            pk.x = *(unsigned*)&h0; pk.y = *(unsigned*)&h1;
            pk.z = *(unsigned*)&h2; pk.w = *(unsigned*)&h3;
            *(uint4*)(Yb + (size_t)n * RR + rg * 8) = pk;
        }
    }
}

// ---------------- gather + max-relu epilogue --------------------------------
// Block 256 thr = 8 warps, 64 nodes/block, warp handles 8 nodes serially.
// Per node: 32 independent half2 row-loads (16 k x {i,j}); math fp32,
// relu folded into max floor. (Measured-best gather configuration.)
__global__ __launch_bounds__(256) void gather_kernel(const void* __restrict__ eidx,
                                                     float* __restrict__ out) {
    int bn   = blockIdx.x;               // 0..511
    int b    = bn >> 8;                  // 256 blocks per batch
    int n0   = (bn & 255) * 64;
    int tid  = threadIdx.x;
    int lane = tid & 31;
    int w    = tid >> 5;

    __shared__ int   s_idx[64][2][KK];   // 8 KB
    __shared__ float s_o[64][65];        // padded, conflict-free

    int is64 = g_is64;
    const long long* e64 = (const long long*)eidx;
    const int*       e32 = (const int*)eidx;
    for (int i = tid; i < 64 * KK; i += 256) {
        int ln = i >> 4, k = i & 15;
        size_t bj = ((size_t)(0 * BB + b) * NN + (n0 + ln)) * KK + k;
        size_t bi = ((size_t)(1 * BB + b) * NN + (n0 + ln)) * KK + k;
        int vi, vj;
        if (is64) { vj = (int)e64[bj]; vi = (int)e64[bi]; }
        else      { vj = e32[bj];      vi = e32[bi]; }
        s_idx[ln][0][k] = vi;            // center   (edge_index[1])
        s_idx[ln][1][k] = vj;            // neighbor (edge_index[0])
    }
    __syncthreads();

    float2 cv = ((const float2*)g_cvec[b])[lane];   // channels 2*lane, 2*lane+1
    const __half* Yb = g_Yh + (size_t)b * NN * RR;

    for (int t = 0; t < 8; t++) {
        int ln = w * 8 + t;
        float m0 = 0.f, m1 = 0.f;        // relu floor folded into max
        #pragma unroll
        for (int k = 0; k < KK; k++) {
            int i = s_idx[ln][0][k];
            int j = s_idx[ln][1][k];
            __half2 hi = ((const __half2*)(Yb + (size_t)i * RR))[lane];
            __half2 hj = ((const __half2*)(Yb + (size_t)j * RR + 64))[lane];
            float2 fi = __half22float2(hi);
            float2 fj = __half22float2(hj);
            m0 = fmaxf(m0, fi.x + fj.x + cv.x);
            m1 = fmaxf(m1, fi.y + fj.y + cv.y);
        }
        s_o[ln][2 * lane]     = m0;
        s_o[ln][2 * lane + 1] = m1;
    }
    __syncthreads();

    float* ob = out + (size_t)b * COUT * NN;
    for (int i = tid; i < COUT * 64; i += 256) {
        int ch = i >> 6, j = i & 63;
        ob[ch * NN + n0 + j] = s_o[j][ch];
    }
}

// ---------------- launch ----------------------------------------------------
extern "C" void kernel_launch(void* const* d_in, const int* in_sizes, int n_in,
                              void* d_out, int out_size) {
    const float* x    = (const float*)d_in[0];
    const void*  eidx = d_in[1];
    const float* W    = (const float*)d_in[2];
    const float* bias = (const float*)d_in[3];
    float* out = (float*)d_out;

    mean_kernel<<<BB * CC, 256>>>(x);
    prep_kernel<<<1, 128>>>(W, bias, eidx);
    gemm_kernel<<<dim3(NN / TNB, BB), 256>>>(x);
    gather_kernel<<<BB * NN / 64, 256>>>(eidx, out);
}